// round 3
// baseline (speedup 1.0000x reference)
#include <cuda_runtime.h>
#include <cstdint>

#define DD    2048     // embedding dim
#define NN1   160      // lora width
#define SROWS 66       // 2 + HEAD_SIZE

typedef unsigned long long ull;

// Static device scratch (no allocations allowed).
// Partial sums for K-split GEMM1, and tanh'ed hidden H.
__device__ float g_part[2][16384 * NN1];   // 2 * 16384 * 160 * 4B = 21 MB
__device__ float g_H[16384 * NN1];         // 10.5 MB

// ---- packed f32x2 helpers (sm_100+ PTX; ptxas never auto-fuses these) ----
__device__ __forceinline__ ull pack2(float v) {
    ull r;
    asm("mov.b64 %0, {%1, %1};" : "=l"(r) : "f"(v));
    return r;
}
__device__ __forceinline__ void fma2(ull &acc, ull a, ull b) {
    asm("fma.rn.f32x2 %0, %1, %2, %0;" : "+l"(acc) : "l"(a), "l"(b));
}
__device__ __forceinline__ void unpack2(ull v, float &lo, float &hi) {
    asm("mov.b64 {%0, %1}, %2;" : "=f"(lo), "=f"(hi) : "l"(v));
}

// ============================================================================
// Kernel 1: fused token-shift + xx = x + sx*tmx + GEMM1 partial
//   C[m,n] = sum_k xx[m,k] * W1[k,n],  K split in 2 halves across blockIdx.y.
//   BM=64, BN=160 (full), BK=16, 128 threads, per-thread 16M x 5N via f32x2.
// ============================================================================
__global__ __launch_bounds__(128) void k_gemm1(
    const float* __restrict__ x, const float* __restrict__ state,
    const float* __restrict__ tmx, const float* __restrict__ w1,
    const int* __restrict__ ip, int S)
{
    const int m0   = blockIdx.x * 64;
    const int kbeg = blockIdx.y * (DD / 2);
    const int i1   = SROWS * ip[0] + 1;

    __shared__ __align__(16) float As[16][66];    // [k][m], pad->conflict-free, 8B-aligned pairs
    __shared__ __align__(16) float Bs[16][NN1];   // [k][n]

    const int tx   = threadIdx.x;
    const int n0   = (tx & 31) * 5;     // 5 consecutive n per thread (5 coprime 32 -> no LDS conflicts)
    const int mb   = (tx >> 5) * 16;    // 16 M-rows per thread (warp-uniform -> LDS broadcast)
    const int lrow = tx >> 2;
    const int lk4  = (tx & 3) * 4;

    ull acc[40];
#pragma unroll
    for (int i = 0; i < 40; ++i) acc[i] = 0ull;

    for (int kt = 0; kt < DD / 2; kt += 16) {
        const int k0 = kbeg + kt;
        const float4 tv = *(const float4*)(tmx + k0 + lk4);
#pragma unroll
        for (int pass = 0; pass < 2; ++pass) {
            const int ml = lrow + pass * 32;
            const int m  = m0 + ml;
            const float4 xv = *(const float4*)(x + (size_t)m * DD + k0 + lk4);
            float4 pv;
            if ((m % S) == 0) {  // first token of a batch: shift comes from state row i1
                const int b = m / S;
                pv = *(const float4*)(state + ((size_t)b * SROWS + i1) * DD + k0 + lk4);
            } else {
                pv = *(const float4*)(x + (size_t)(m - 1) * DD + k0 + lk4);
            }
            // xx = x + (xprev - x) * tmx
            As[lk4 + 0][ml] = fmaf(pv.x - xv.x, tv.x, xv.x);
            As[lk4 + 1][ml] = fmaf(pv.y - xv.y, tv.y, xv.y);
            As[lk4 + 2][ml] = fmaf(pv.z - xv.z, tv.z, xv.z);
            As[lk4 + 3][ml] = fmaf(pv.w - xv.w, tv.w, xv.w);
        }
#pragma unroll
        for (int i = 0; i < 5; ++i) {
            const int idx = tx + i * 128;          // 640 float4 total, exact
            const int kk  = idx / 40;
            const int n4  = (idx - kk * 40) * 4;
            *(float4*)&Bs[kk][n4] = *(const float4*)(w1 + (size_t)(k0 + kk) * NN1 + n4);
        }
        __syncthreads();
#pragma unroll
        for (int kk = 0; kk < 16; ++kk) {
            ull bb[5];
#pragma unroll
            for (int j = 0; j < 5; ++j) bb[j] = pack2(Bs[kk][n0 + j]);
#pragma unroll
            for (int p = 0; p < 8; ++p) {
                const ull ap = *(const ull*)&As[kk][mb + 2 * p];   // broadcast LDS.64
#pragma unroll
                for (int j = 0; j < 5; ++j) fma2(acc[p * 5 + j], ap, bb[j]);
            }
        }
        __syncthreads();
    }

    float* dst = g_part[blockIdx.y];
#pragma unroll
    for (int p = 0; p < 8; ++p) {
        const int m = m0 + mb + 2 * p;
#pragma unroll
        for (int j = 0; j < 5; ++j) {
            float lo, hi;
            unpack2(acc[p * 5 + j], lo, hi);
            dst[(size_t)m * NN1 + n0 + j]       = lo;
            dst[(size_t)(m + 1) * NN1 + n0 + j] = hi;
        }
    }
}

// ============================================================================
// Kernel 1b: reduce K-split partials + tanh -> H
// ============================================================================
__global__ void k_act(int total)
{
    const int idx = blockIdx.x * blockDim.x + threadIdx.x;
    if (idx < total) g_H[idx] = tanhf(g_part[0][idx] + g_part[1][idx]);
}

// ============================================================================
// Kernel 2: GEMM2 + combine + output
//   out[m,f,d] = x[m,d] + sx[m,d]*(maa_f[d] + sum_k H[m,f*32+k]*W2[f,k,d])
//   CTA: 32 tokens x 512 d, loop f. H tile held as duplicated f32x2 in smem.
//   Thread: 4 tokens x 16 d (8 f32x2 accumulators per token).
// ============================================================================
__global__ __launch_bounds__(256, 2) void k_gemm2(
    const float* __restrict__ x, const float* __restrict__ state,
    const float* __restrict__ w2,
    const float* __restrict__ mk, const float* __restrict__ mw,
    const float* __restrict__ mv, const float* __restrict__ mr,
    const float* __restrict__ mg,
    const int* __restrict__ ip, float* __restrict__ out, int S)
{
    const int m0    = blockIdx.x * 32;
    const int dbase = blockIdx.y * 512;
    const int tx    = threadIdx.x;
    const int tg    = tx >> 5;           // token group (warp-uniform -> LDS broadcast)
    const int dg    = tx & 31;
    const int dloc  = dbase + dg * 16;
    const int i1    = SROWS * ip[0] + 1;

    __shared__ __align__(16) ull Hs[32][NN1];   // 40 KB, h duplicated into both f32x2 lanes

    for (int i = tx; i < 32 * NN1; i += 256) {
        const int tl = i / NN1;
        const int n  = i - tl * NN1;
        Hs[tl][n] = pack2(g_H[(size_t)(m0 + tl) * NN1 + n]);
    }
    __syncthreads();

#pragma unroll 1
    for (int f = 0; f < 5; ++f) {
        ull acc[4][8];
#pragma unroll
        for (int j = 0; j < 4; ++j)
#pragma unroll
            for (int p = 0; p < 8; ++p) acc[j][p] = 0ull;

        const float* w2f = w2 + (size_t)(f * 32) * DD + dloc;
#pragma unroll 2
        for (int k = 0; k < 32; ++k) {
            const ull* wp = (const ull*)(w2f + (size_t)k * DD);   // 64B-aligned
            ull w[8];
            {
                const ulonglong2 a = *(const ulonglong2*)(wp + 0);
                const ulonglong2 b = *(const ulonglong2*)(wp + 2);
                const ulonglong2 c = *(const ulonglong2*)(wp + 4);
                const ulonglong2 d = *(const ulonglong2*)(wp + 6);
                w[0] = a.x; w[1] = a.y; w[2] = b.x; w[3] = b.y;
                w[4] = c.x; w[5] = c.y; w[6] = d.x; w[7] = d.y;
            }
#pragma unroll
            for (int j = 0; j < 4; ++j) {
                const ull h = Hs[tg * 4 + j][f * 32 + k];
#pragma unroll
                for (int p = 0; p < 8; ++p) fma2(acc[j][p], w[p], h);
            }
        }

        // epilogue: out = x + (xprev - x) * (maa + acc)
        const float* maa = (f == 0 ? mk : f == 1 ? mw : f == 2 ? mv : f == 3 ? mr : mg) + dloc;
        float4 mav[4];
#pragma unroll
        for (int q = 0; q < 4; ++q) mav[q] = *(const float4*)(maa + q * 4);

#pragma unroll
        for (int j = 0; j < 4; ++j) {
            const int m = m0 + tg * 4 + j;
            const float* xr = x + (size_t)m * DD + dloc;
            const float* pr;
            if ((m % S) == 0) {
                pr = state + ((size_t)(m / S) * SROWS + i1) * DD + dloc;
            } else {
                pr = x + (size_t)(m - 1) * DD + dloc;
            }
            float* orow = out + ((size_t)m * 5 + f) * DD + dloc;
#pragma unroll
            for (int q = 0; q < 4; ++q) {
                const float4 xv = *(const float4*)(xr + q * 4);
                const float4 pv = *(const float4*)(pr + q * 4);
                float a0, a1, a2, a3;
                unpack2(acc[j][2 * q + 0], a0, a1);
                unpack2(acc[j][2 * q + 1], a2, a3);
                const float4 mm = mav[q];
                float4 o;
                o.x = fmaf(pv.x - xv.x, mm.x + a0, xv.x);
                o.y = fmaf(pv.y - xv.y, mm.y + a1, xv.y);
                o.z = fmaf(pv.z - xv.z, mm.z + a2, xv.z);
                o.w = fmaf(pv.w - xv.w, mm.w + a3, xv.w);
                *(float4*)(orow + q * 4) = o;
            }
        }
    }
}

// ============================================================================
// Kernel 3: new_state = state with row i1 replaced by x[:, S-1, :]
// ============================================================================
__global__ void k_state(const float* __restrict__ x, const float* __restrict__ state,
                        const int* __restrict__ ip, float* __restrict__ out2,
                        int S, int total)
{
    const int idx = blockIdx.x * blockDim.x + threadIdx.x;
    if (idx >= total) return;
    const int i1 = SROWS * ip[0] + 1;
    const int d  = idx & (DD - 1);
    const int r  = (idx / DD) % SROWS;
    const int b  = idx / (DD * SROWS);
    float v;
    if (r == i1) v = x[((size_t)b * S + (S - 1)) * DD + d];
    else         v = state[idx];
    out2[idx] = v;
}

// ============================================================================
extern "C" void kernel_launch(void* const* d_in, const int* in_sizes, int n_in,
                              void* d_out, int out_size)
{
    const float* x     = (const float*)d_in[0];
    const float* state = (const float*)d_in[1];
    const float* tmx   = (const float*)d_in[2];
    const float* w1    = (const float*)d_in[3];
    const float* w2    = (const float*)d_in[4];
    const float* mk    = (const float*)d_in[5];
    const float* mw    = (const float*)d_in[6];
    const float* mv    = (const float*)d_in[7];
    const float* mr    = (const float*)d_in[8];
    const float* mg    = (const float*)d_in[9];
    const int*   ip    = (const int*)  d_in[10];
    float* out = (float*)d_out;

    const int B = in_sizes[1] / (SROWS * DD);
    const int S = in_sizes[0] / (B * DD);
    const int M = B * S;

    k_gemm1<<<dim3(M / 64, 2), 128>>>(x, state, tmx, w1, ip, S);
    k_act<<<(M * NN1 + 255) / 256, 256>>>(M * NN1);
    k_gemm2<<<dim3(M / 32, DD / 512), 256>>>(x, state, w2, mk, mw, mv, mr, mg, ip, out, S);

    const long long kw = (long long)M * 5 * DD;
    const int st_total = B * SROWS * DD;
    if ((long long)out_size >= kw + (long long)st_total) {
        k_state<<<(st_total + 255) / 256, 256>>>(x, state, ip, out + kw, S, st_total);
    }
}

// round 8
// speedup vs baseline: 2.0238x; 2.0238x over previous
#include <cuda_runtime.h>
#include <cstdint>

#define DD    2048     // embedding dim
#define NN1   160      // lora width
#define SROWS 66       // 2 + HEAD_SIZE

typedef unsigned long long ull;

// Static device scratch (no allocations allowed).
__device__ float g_part[2][8192 * NN1];    // K-split partials for GEMM1
__device__ float g_H[8192 * NN1];          // tanh'ed hidden

// ---- packed f32x2 helpers (sm_100+; ptxas never auto-fuses these) ----
__device__ __forceinline__ ull pack2(float v) {               // duplicate
    ull r; asm("mov.b64 %0, {%1, %1};" : "=l"(r) : "f"(v)); return r;
}
__device__ __forceinline__ ull pack_pair(float lo, float hi) { // genuine pair
    ull r; asm("mov.b64 %0, {%1, %2};" : "=l"(r) : "f"(lo), "f"(hi)); return r;
}
__device__ __forceinline__ void fma2(ull &acc, ull a, ull b) {
    asm("fma.rn.f32x2 %0, %1, %2, %0;" : "+l"(acc) : "l"(a), "l"(b));
}
__device__ __forceinline__ void unpack2(ull v, float &lo, float &hi) {
    asm("mov.b64 {%0, %1}, %2;" : "=f"(lo), "=f"(hi) : "l"(v));
}

// ============================================================================
// Kernel 1: fused token-shift + xx = x + sx*tmx, then GEMM1 partial
//   C[m,n] = sum_k xx[m,k] * W1[k,n], K split in 2 across blockIdx.y.
//   BM=64, BN=160 (full), BK=16, 128 threads, per-thread 16M x 5N via f32x2.
//   B tile staged PRE-DUPLICATED as f32x2 -> inner loop is pure LDS.64 + FFMA2.
// ============================================================================
__global__ __launch_bounds__(128) void k_gemm1(
    const float* __restrict__ x, const float* __restrict__ state,
    const float* __restrict__ tmx, const float* __restrict__ w1,
    const int* __restrict__ ip, int S)
{
    const int m0   = blockIdx.x * 64;
    const int kbeg = blockIdx.y * (DD / 2);
    const int i1   = SROWS * ip[0] + 1;

    __shared__ __align__(16) float As[16][66];    // [k][m], padded
    __shared__ __align__(16) ull   Bsu[16][NN1];  // [k][n], duplicated f32x2 (20.5 KB)

    const int tx   = threadIdx.x;
    const int n0   = (tx & 31) * 5;     // 5 consecutive n per thread
    const int mb   = (tx >> 5) * 16;    // 16 M-rows per thread (warp-uniform -> LDS broadcast)
    const int lrow = tx >> 2;
    const int lk4  = (tx & 3) * 4;

    ull acc[40];
#pragma unroll
    for (int i = 0; i < 40; ++i) acc[i] = 0ull;

    for (int kt = 0; kt < DD / 2; kt += 16) {
        const int k0 = kbeg + kt;
        const float4 tv = *(const float4*)(tmx + k0 + lk4);
#pragma unroll
        for (int pass = 0; pass < 2; ++pass) {
            const int ml = lrow + pass * 32;
            const int m  = m0 + ml;
            const float4 xv = *(const float4*)(x + (size_t)m * DD + k0 + lk4);
            float4 pv;
            if ((m % S) == 0) {
                const int b = m / S;
                pv = *(const float4*)(state + ((size_t)b * SROWS + i1) * DD + k0 + lk4);
            } else {
                pv = *(const float4*)(x + (size_t)(m - 1) * DD + k0 + lk4);
            }
            As[lk4 + 0][ml] = fmaf(pv.x - xv.x, tv.x, xv.x);
            As[lk4 + 1][ml] = fmaf(pv.y - xv.y, tv.y, xv.y);
            As[lk4 + 2][ml] = fmaf(pv.z - xv.z, tv.z, xv.z);
            As[lk4 + 3][ml] = fmaf(pv.w - xv.w, tv.w, xv.w);
        }
#pragma unroll
        for (int i = 0; i < 5; ++i) {
            const int idx = tx + i * 128;          // 640 float4 total
            const int kk  = idx / 40;
            const int n4  = (idx - kk * 40) * 4;
            const float4 v = *(const float4*)(w1 + (size_t)(k0 + kk) * NN1 + n4);
            ulonglong2 s0; s0.x = pack2(v.x); s0.y = pack2(v.y);
            ulonglong2 s1; s1.x = pack2(v.z); s1.y = pack2(v.w);
            *(ulonglong2*)&Bsu[kk][n4 + 0] = s0;
            *(ulonglong2*)&Bsu[kk][n4 + 2] = s1;
        }
        __syncthreads();
#pragma unroll
        for (int kk = 0; kk < 16; ++kk) {
            ull bb[5];
#pragma unroll
            for (int j = 0; j < 5; ++j) bb[j] = Bsu[kk][n0 + j];   // LDS.64
#pragma unroll
            for (int p = 0; p < 8; ++p) {
                const ull ap = *(const ull*)&As[kk][mb + 2 * p];   // broadcast LDS.64
#pragma unroll
                for (int j = 0; j < 5; ++j) fma2(acc[p * 5 + j], ap, bb[j]);
            }
        }
        __syncthreads();
    }

    float* dst = g_part[blockIdx.y];
#pragma unroll
    for (int p = 0; p < 8; ++p) {
        const int m = m0 + mb + 2 * p;
#pragma unroll
        for (int j = 0; j < 5; ++j) {
            float lo, hi;
            unpack2(acc[p * 5 + j], lo, hi);
            dst[(size_t)m * NN1 + n0 + j]       = lo;
            dst[(size_t)(m + 1) * NN1 + n0 + j] = hi;
        }
    }
}

// ============================================================================
// Kernel 1b: reduce K-split partials + fast tanh -> H   (float4 vectorized)
// ============================================================================
__device__ __forceinline__ float ftanh(float v) {
    v = fminf(fmaxf(v, -10.f), 10.f);
    const float e = __expf(2.f * v);
    return __fdividef(e - 1.f, e + 1.f);
}

__global__ void k_act(int total4)
{
    const int idx = blockIdx.x * blockDim.x + threadIdx.x;
    if (idx >= total4) return;
    const float4 a = ((const float4*)g_part[0])[idx];
    const float4 b = ((const float4*)g_part[1])[idx];
    float4 o;
    o.x = ftanh(a.x + b.x); o.y = ftanh(a.y + b.y);
    o.z = ftanh(a.z + b.z); o.w = ftanh(a.w + b.w);
    ((float4*)g_H)[idx] = o;
}

// ============================================================================
// Kernel 2: GEMM2 + combine + output
//   out[m,f,d] = x[m,d] + sx[m,d]*(maa_f[d] + sum_k H[m,f*32+k]*W2[f,k,d])
//   CTA: 64 tokens x 256 d, loop over f. w2 tile staged in smem as f32x2
//   PAIRS (shared by all 8 warps), H f-slice staged duplicated.
//   Thread: 8 tokens (warp-uniform group) x 8 d (4 f32x2 accs per token).
// ============================================================================
__global__ __launch_bounds__(256, 2) void k_gemm2(
    const float* __restrict__ x, const float* __restrict__ state,
    const float* __restrict__ w2,
    const float* __restrict__ mk, const float* __restrict__ mw,
    const float* __restrict__ mv, const float* __restrict__ mr,
    const float* __restrict__ mg,
    const int* __restrict__ ip, float* __restrict__ out, int S)
{
    const int m0    = blockIdx.x * 64;
    const int dbase = blockIdx.y * 256;
    const int tx    = threadIdx.x;
    const int tg    = tx >> 5;          // token group (warp-uniform)
    const int dg    = tx & 31;          // d-pair lane
    const int i1    = SROWS * ip[0] + 1;

    __shared__ __align__(16) ull Wsu[32 * 128];   // 32 KB: Wsu[k*128+p] = (w2[..,2p], w2[..,2p+1])
    __shared__ __align__(16) ull Hsf[64 * 32];    // 16 KB: Hsf[tok*32+k] = dup(h)

#pragma unroll 1
    for (int f = 0; f < 5; ++f) {
        __syncthreads();   // protect smem reuse across f-phases

        // stage w2[f, 0:32, dtile] as genuine pairs (coalesced float4 loads)
        const float* w2f = w2 + (size_t)(f * 32) * DD + dbase;
#pragma unroll
        for (int it = 0; it < 8; ++it) {
            const int idx = tx + it * 256;        // 0..2047 float4s
            const int k   = idx >> 6;             // 64 float4 per 256-float row
            const int q4  = idx & 63;
            const float4 v = *(const float4*)(w2f + (size_t)k * DD + q4 * 4);
            ulonglong2 s;
            s.x = pack_pair(v.x, v.y);
            s.y = pack_pair(v.z, v.w);
            *(ulonglong2*)&Wsu[k * 128 + q4 * 2] = s;
        }
        // stage H f-slice duplicated (coalesced 32-float rows)
#pragma unroll
        for (int it = 0; it < 8; ++it) {
            const int idx = tx + it * 256;        // tok*32 + k
            const int tok = idx >> 5;
            const int k   = idx & 31;
            Hsf[idx] = pack2(g_H[(size_t)(m0 + tok) * NN1 + f * 32 + k]);
        }
        __syncthreads();

        ull acc[8][4];
#pragma unroll
        for (int j = 0; j < 8; ++j)
#pragma unroll
            for (int c = 0; c < 4; ++c) acc[j][c] = 0ull;

#pragma unroll 4
        for (int k = 0; k < 32; ++k) {
            const ull* wr = &Wsu[k * 128 + dg];
            const ull w0 = wr[0], w1 = wr[32], w2v = wr[64], w3 = wr[96];  // 2-phase LDS.64
            const ull* hc = &Hsf[(tg * 8) * 32 + k];
#pragma unroll
            for (int j = 0; j < 8; ++j) {
                const ull h = hc[j * 32];          // broadcast LDS.64
                fma2(acc[j][0], w0, h);
                fma2(acc[j][1], w1, h);
                fma2(acc[j][2], w2v, h);
                fma2(acc[j][3], w3, h);
            }
        }

        // epilogue: out = x + (xprev - x) * (maa + acc)
        const float* maa = (f == 0 ? mk : f == 1 ? mw : f == 2 ? mv : f == 3 ? mr : mg);
        float2 mav[4];
#pragma unroll
        for (int c = 0; c < 4; ++c)
            mav[c] = *(const float2*)(maa + dbase + 2 * (dg + 32 * c));

#pragma unroll
        for (int j = 0; j < 8; ++j) {
            const int m = m0 + tg * 8 + j;
            const float* xr = x + (size_t)m * DD + dbase;
            const float* pr = ((m % S) == 0)
                ? state + ((size_t)(m / S) * SROWS + i1) * DD + dbase
                : xr - DD;
            float* orow = out + ((size_t)m * 5 + f) * DD + dbase;
#pragma unroll
            for (int c = 0; c < 4; ++c) {
                const int off = 2 * (dg + 32 * c);
                const float2 xv = *(const float2*)(xr + off);
                const float2 pv = *(const float2*)(pr + off);
                float a0, a1;
                unpack2(acc[j][c], a0, a1);
                float2 o;
                o.x = fmaf(pv.x - xv.x, mav[c].x + a0, xv.x);
                o.y = fmaf(pv.y - xv.y, mav[c].y + a1, xv.y);
                *(float2*)(orow + off) = o;       // coalesced 256B per warp-store
            }
        }
    }
}

// ============================================================================
// Kernel 3: new_state = state with row i1 replaced by x[:, S-1, :]  (float4)
// ============================================================================
__global__ void k_state(const float* __restrict__ x, const float* __restrict__ state,
                        const int* __restrict__ ip, float* __restrict__ out2,
                        int S, int total4)
{
    const int idx = blockIdx.x * blockDim.x + threadIdx.x;
    if (idx >= total4) return;
    const int i1 = SROWS * ip[0] + 1;
    const int D4 = DD / 4;
    const int d4 = idx & (D4 - 1);
    const int r  = (idx / D4) % SROWS;
    const int b  = idx / (D4 * SROWS);
    float4 v;
    if (r == i1) v = ((const float4*)x)[((size_t)b * S + (S - 1)) * D4 + d4];
    else         v = ((const float4*)state)[idx];
    ((float4*)out2)[idx] = v;
}

// ============================================================================
extern "C" void kernel_launch(void* const* d_in, const int* in_sizes, int n_in,
                              void* d_out, int out_size)
{
    const float* x     = (const float*)d_in[0];
    const float* state = (const float*)d_in[1];
    const float* tmx   = (const float*)d_in[2];
    const float* w1    = (const float*)d_in[3];
    const float* w2    = (const float*)d_in[4];
    const float* mk    = (const float*)d_in[5];
    const float* mw    = (const float*)d_in[6];
    const float* mv    = (const float*)d_in[7];
    const float* mr    = (const float*)d_in[8];
    const float* mg    = (const float*)d_in[9];
    const int*   ip    = (const int*)  d_in[10];
    float* out = (float*)d_out;

    const int B = in_sizes[1] / (SROWS * DD);
    const int S = in_sizes[0] / (B * DD);
    const int M = B * S;

    k_gemm1<<<dim3(M / 64, 2), 128>>>(x, state, tmx, w1, ip, S);

    const int act4 = (M * NN1) / 4;
    k_act<<<(act4 + 255) / 256, 256>>>(act4);

    k_gemm2<<<dim3(M / 64, DD / 256), 256>>>(x, state, w2, mk, mw, mv, mr, mg, ip, out, S);

    const long long kw = (long long)M * 5 * DD;
    const int st_total = B * SROWS * DD;
    if ((long long)out_size >= kw + (long long)st_total) {
        k_state<<<(st_total / 4 + 255) / 256, 256>>>(x, state, ip, out + kw, S, st_total / 4);
    }
}